// round 1
// baseline (speedup 1.0000x reference)
#include <cuda_runtime.h>
#include <math.h>

#define Bdim 2
#define Nseq 2048
#define Dm   1024
#define Hh   16
#define HDd  64
#define ROWS (Bdim*Nseq)   /* 4096 */

// ---- scratch (static device globals; no allocation allowed) ----
__device__ float g_q[ROWS*Dm];
__device__ float g_k[ROWS*Dm];
__device__ float g_v[ROWS*Dm];
__device__ float g_a[ROWS*Dm];
__device__ float g_f[ROWS*Hh];
__device__ float g_gm[ROWS*Hh];
__device__ float g_g1[ROWS*HDd];
__device__ float g_attn[ROWS*Dm];
__device__ float g_ln[ROWS*Dm];

__device__ __forceinline__ float sigmoidf_(float z) { return 1.f / (1.f + expf(-z)); }

// ============================================================
// Tiled fp32 GEMM: C[M,N] = act(A[M,K] @ B[K,N])
// BM=BN=128, BK=16, 256 threads, 8x8 per thread.
// M,N,K all divisible by tile sizes here.
// act: 0 = none, 1 = silu
// ============================================================
__global__ __launch_bounds__(256) void sgemm_k(
    const float* __restrict__ A, const float* __restrict__ B,
    float* __restrict__ C, int M, int N, int K, int act)
{
    __shared__ float As[16][128];
    __shared__ float Bs[16][128];

    const int tid = threadIdx.x;
    const int m0 = blockIdx.y * 128;
    const int n0 = blockIdx.x * 128;
    const int tx = tid & 15;     // 0..15 -> n
    const int ty = tid >> 4;     // 0..15 -> m

    const int ar = tid >> 2;          // 0..63
    const int ac = (tid & 3) * 4;     // 0,4,8,12
    const int br = tid >> 5;          // 0..7
    const int bc = (tid & 31) * 4;    // 0..124

    float acc[8][8];
#pragma unroll
    for (int i = 0; i < 8; i++)
#pragma unroll
        for (int j = 0; j < 8; j++) acc[i][j] = 0.f;

    for (int k0 = 0; k0 < K; k0 += 16) {
#pragma unroll
        for (int p = 0; p < 2; p++) {
            float4 va = *(const float4*)&A[(size_t)(m0 + ar + p*64) * K + k0 + ac];
            As[ac+0][ar + p*64] = va.x;
            As[ac+1][ar + p*64] = va.y;
            As[ac+2][ar + p*64] = va.z;
            As[ac+3][ar + p*64] = va.w;
        }
#pragma unroll
        for (int p = 0; p < 2; p++) {
            *(float4*)&Bs[br + p*8][bc] =
                *(const float4*)&B[(size_t)(k0 + br + p*8) * N + n0 + bc];
        }
        __syncthreads();

#pragma unroll
        for (int kk = 0; kk < 16; kk++) {
            float a[8], b[8];
            *(float4*)&a[0] = *(const float4*)&As[kk][ty*8];
            *(float4*)&a[4] = *(const float4*)&As[kk][ty*8 + 4];
            *(float4*)&b[0] = *(const float4*)&Bs[kk][tx*8];
            *(float4*)&b[4] = *(const float4*)&Bs[kk][tx*8 + 4];
#pragma unroll
            for (int i = 0; i < 8; i++)
#pragma unroll
                for (int j = 0; j < 8; j++)
                    acc[i][j] = fmaf(a[i], b[j], acc[i][j]);
        }
        __syncthreads();
    }

#pragma unroll
    for (int i = 0; i < 8; i++) {
#pragma unroll
        for (int j = 0; j < 8; j++) {
            float z = acc[i][j];
            if (act == 1) z = z * sigmoidf_(z);   // silu
            C[(size_t)(m0 + ty*8 + i) * N + n0 + tx*8 + j] = z;
        }
    }
}

// ============================================================
// Small projections: f = sigmoid(x@Wf), gamma = -sigmoid(x@Wgamma),
// g1 = x@Wg1. One block per row, 128 threads (96 active for dots).
// ============================================================
__global__ __launch_bounds__(128) void proj_small_k(
    const float* __restrict__ x, const float* __restrict__ Wgamma,
    const float* __restrict__ Wf, const float* __restrict__ Wg1)
{
    const int row = blockIdx.x;
    const int tid = threadIdx.x;
    __shared__ float sx[Dm];
#pragma unroll
    for (int j = 0; j < 2; j++)
        *(float4*)&sx[tid*4 + j*512] = *(const float4*)&x[(size_t)row*Dm + tid*4 + j*512];
    __syncthreads();

    const int j = tid;
    if (j < 16) {
        float a0=0,a1=0,a2=0,a3=0;
        for (int d = 0; d < Dm; d += 4) {
            a0 = fmaf(sx[d+0], Wf[(d+0)*Hh + j], a0);
            a1 = fmaf(sx[d+1], Wf[(d+1)*Hh + j], a1);
            a2 = fmaf(sx[d+2], Wf[(d+2)*Hh + j], a2);
            a3 = fmaf(sx[d+3], Wf[(d+3)*Hh + j], a3);
        }
        g_f[row*Hh + j] = sigmoidf_((a0+a1)+(a2+a3));   // exp(log_sigmoid(z)) == sigmoid(z)
    } else if (j < 32) {
        const int jj = j - 16;
        float a0=0,a1=0,a2=0,a3=0;
        for (int d = 0; d < Dm; d += 4) {
            a0 = fmaf(sx[d+0], Wgamma[(d+0)*Hh + jj], a0);
            a1 = fmaf(sx[d+1], Wgamma[(d+1)*Hh + jj], a1);
            a2 = fmaf(sx[d+2], Wgamma[(d+2)*Hh + jj], a2);
            a3 = fmaf(sx[d+3], Wgamma[(d+3)*Hh + jj], a3);
        }
        g_gm[row*Hh + jj] = -sigmoidf_((a0+a1)+(a2+a3));
    } else if (j < 96) {
        const int jj = j - 32;
        float a0=0,a1=0,a2=0,a3=0;
        for (int d = 0; d < Dm; d += 4) {
            a0 = fmaf(sx[d+0], Wg1[(d+0)*HDd + jj], a0);
            a1 = fmaf(sx[d+1], Wg1[(d+1)*HDd + jj], a1);
            a2 = fmaf(sx[d+2], Wg1[(d+2)*HDd + jj], a2);
            a3 = fmaf(sx[d+3], Wg1[(d+3)*HDd + jj], a3);
        }
        g_g1[row*HDd + jj] = (a0+a1)+(a2+a3);
    }
}

// ============================================================
// Prep: l2-normalize k per head, a = k_norm * gamma * f.
// One warp per (row, head).
// ============================================================
__global__ __launch_bounds__(256) void prep_k()
{
    const int w    = blockIdx.x * 8 + (threadIdx.x >> 5);
    const int lane = threadIdx.x & 31;
    const int bn = w >> 4, h = w & 15;
    const size_t base = (size_t)bn * Dm + h * HDd;
    float k0 = g_k[base + lane];
    float k1 = g_k[base + lane + 32];
    float ss = k0*k0 + k1*k1;
#pragma unroll
    for (int o = 16; o; o >>= 1) ss += __shfl_xor_sync(0xffffffffu, ss, o);
    const float inv = 1.f / fmaxf(sqrtf(ss), 1e-12f);
    const float sc  = g_gm[bn*Hh + h] * g_f[bn*Hh + h];
    k0 *= inv; k1 *= inv;
    g_k[base + lane]      = k0;
    g_k[base + lane + 32] = k1;
    g_a[base + lane]      = k0 * sc;
    g_a[base + lane + 32] = k1 * sc;
}

// ============================================================
// Sequential DPLR delta-rule scan.
// One block per (b,h). 256 threads = 64 columns x 4 sublanes.
// Each thread holds 16 rows of the 64x64 state S[k][v] in registers.
// 8-step chunks staged in shared memory.
// ============================================================
__global__ __launch_bounds__(256) void scan_k()
{
    const int z = blockIdx.x;           // 0..31
    const int b = z >> 4, h = z & 15;
    const int tid = threadIdx.x;
    const int col = tid >> 2;           // v index 0..63
    const int sub = tid & 3;            // row group
    const int rb  = sub * 16;
    const unsigned FULL = 0xffffffffu;

    const int CH = 8;
    __shared__ float sq[CH][64], sk[CH][64], sv[CH][64], sa[CH][64], sf[CH];

    float S[16];
#pragma unroll
    for (int r = 0; r < 16; r++) S[r] = 0.f;

    const size_t base = (size_t)b * Nseq * Dm + h * HDd;

    for (int t0 = 0; t0 < Nseq; t0 += CH) {
        __syncthreads();
#pragma unroll
        for (int j = tid; j < CH*64; j += 256) {
            const int i = j >> 6, e = j & 63;
            const size_t g = base + (size_t)(t0 + i) * Dm + e;
            sq[i][e] = g_q[g];
            sk[i][e] = g_k[g];
            sv[i][e] = g_v[g];
            sa[i][e] = g_a[g];
        }
        if (tid < CH) sf[tid] = g_f[((size_t)b*Nseq + t0 + tid) * Hh + h];
        __syncthreads();

        for (int i = 0; i < CH; i++) {
            const float f = sf[i];
            float u0 = 0.f, u1 = 0.f;
#pragma unroll
            for (int r = 0; r < 16; r++) {
                const float t = f * S[r];
                S[r] = t;
                if (r & 1) u1 = fmaf(sa[i][rb + r], t, u1);
                else       u0 = fmaf(sa[i][rb + r], t, u0);
            }
            float u = u0 + u1;
            u += __shfl_xor_sync(FULL, u, 1);
            u += __shfl_xor_sync(FULL, u, 2);
            u += sv[i][col];
#pragma unroll
            for (int r = 0; r < 16; r++)
                S[r] = fmaf(sk[i][rb + r], u, S[r]);
            float o0 = 0.f, o1 = 0.f;
#pragma unroll
            for (int r = 0; r < 16; r++) {
                if (r & 1) o1 = fmaf(sq[i][rb + r], S[r], o1);
                else       o0 = fmaf(sq[i][rb + r], S[r], o0);
            }
            float o = o0 + o1;
            o += __shfl_xor_sync(FULL, o, 1);
            o += __shfl_xor_sync(FULL, o, 2);
            if (sub == 0)
                g_attn[base + (size_t)(t0 + i) * Dm + col] = o;
        }
    }
}

// ============================================================
// gate = sigmoid(g1 @ Wg2); attn *= gate. One block per row.
// ============================================================
__global__ __launch_bounds__(256) void gate_k(const float* __restrict__ Wg2)
{
    const int row = blockIdx.x;
    const int tid = threadIdx.x;
    __shared__ float sg[HDd];
    if (tid < HDd) sg[tid] = g_g1[row*HDd + tid];
    __syncthreads();
#pragma unroll
    for (int j = 0; j < 4; j++) {
        const int d = tid + j*256;
        float a0 = 0.f, a1 = 0.f;
#pragma unroll
        for (int kk = 0; kk < HDd; kk += 2) {
            a0 = fmaf(sg[kk],   Wg2[(size_t)kk*Dm + d],     a0);
            a1 = fmaf(sg[kk+1], Wg2[(size_t)(kk+1)*Dm + d], a1);
        }
        const float gv = sigmoidf_(a0 + a1);
        g_attn[(size_t)row*Dm + d] *= gv;
    }
}

// ============================================================
// LayerNorm (weight only) over D. One block per row.
// ============================================================
__global__ __launch_bounds__(256) void ln_k(const float* __restrict__ nw)
{
    const int row = blockIdx.x;
    const int tid = threadIdx.x;
    const int lane = tid & 31, wid = tid >> 5;
    __shared__ float ws[8], ws2[8];

    float vals[4];
    float s = 0.f, s2 = 0.f;
#pragma unroll
    for (int j = 0; j < 4; j++) {
        const float v = g_attn[(size_t)row*Dm + tid + j*256];
        vals[j] = v; s += v; s2 = fmaf(v, v, s2);
    }
#pragma unroll
    for (int o = 16; o; o >>= 1) {
        s  += __shfl_xor_sync(0xffffffffu, s,  o);
        s2 += __shfl_xor_sync(0xffffffffu, s2, o);
    }
    if (lane == 0) { ws[wid] = s; ws2[wid] = s2; }
    __syncthreads();
    float ts = 0.f, ts2 = 0.f;
#pragma unroll
    for (int w = 0; w < 8; w++) { ts += ws[w]; ts2 += ws2[w]; }
    const float mu  = ts * (1.f/Dm);
    const float var = ts2 * (1.f/Dm) - mu*mu;
    const float inv = rsqrtf(var + 1e-5f);
#pragma unroll
    for (int j = 0; j < 4; j++) {
        const int d = tid + j*256;
        g_ln[(size_t)row*Dm + d] = (vals[j] - mu) * inv * nw[d];
    }
}

// ============================================================
extern "C" void kernel_launch(void* const* d_in, const int* in_sizes, int n_in,
                              void* d_out, int out_size)
{
    const float* x      = (const float*)d_in[0];
    const float* Wq     = (const float*)d_in[1];
    const float* Wk     = (const float*)d_in[2];
    const float* Wv     = (const float*)d_in[3];
    const float* Wgamma = (const float*)d_in[4];
    const float* Wf     = (const float*)d_in[5];
    const float* Wg1    = (const float*)d_in[6];
    const float* Wg2    = (const float*)d_in[7];
    const float* Wo     = (const float*)d_in[8];
    const float* nw     = (const float*)d_in[9];
    float* out = (float*)d_out;

    float *q, *k, *v, *ln;
    cudaGetSymbolAddress((void**)&q,  g_q);
    cudaGetSymbolAddress((void**)&k,  g_k);
    cudaGetSymbolAddress((void**)&v,  g_v);
    cudaGetSymbolAddress((void**)&ln, g_ln);

    dim3 gg(Dm/128, ROWS/128);
    sgemm_k<<<gg, 256>>>(x, Wq, q, ROWS, Dm, Dm, 1);
    sgemm_k<<<gg, 256>>>(x, Wk, k, ROWS, Dm, Dm, 1);
    sgemm_k<<<gg, 256>>>(x, Wv, v, ROWS, Dm, Dm, 1);
    proj_small_k<<<ROWS, 128>>>(x, Wgamma, Wf, Wg1);
    prep_k<<<(ROWS*Hh)/8, 256>>>();
    scan_k<<<Bdim*Hh, 256>>>();
    gate_k<<<ROWS, 256>>>(Wg2);
    ln_k<<<ROWS, 256>>>(nw);
    sgemm_k<<<gg, 256>>>(ln, Wo, out, ROWS, Dm, Dm, 0);
}

// round 2
// speedup vs baseline: 1.8039x; 1.8039x over previous
#include <cuda_runtime.h>
#include <cuda_bf16.h>
#include <math.h>

#define Bdim 2
#define Nseq 2048
#define Dm   1024
#define Hh   16
#define HDd  64
#define ROWS (Bdim*Nseq)   /* 4096 */

// ---------------- scratch (static device globals) ----------------
__device__ __nv_bfloat16 g_xh[ROWS*Dm],  g_xl[ROWS*Dm];
__device__ __nv_bfloat16 g_Wqh[Dm*Dm],   g_Wql[Dm*Dm];
__device__ __nv_bfloat16 g_Wkh[Dm*Dm],   g_Wkl[Dm*Dm];
__device__ __nv_bfloat16 g_Wvh[Dm*Dm],   g_Wvl[Dm*Dm];
__device__ __nv_bfloat16 g_Woh[Dm*Dm],   g_Wol[Dm*Dm];
__device__ __nv_bfloat16 g_Wg2h[HDd*Dm], g_Wg2l[HDd*Dm];
__device__ __nv_bfloat16 g_Wsh[Dm*128],  g_Wsl[Dm*128];
__device__ float g_q[ROWS*Dm], g_k[ROWS*Dm], g_v[ROWS*Dm], g_a[ROWS*Dm];
__device__ float g_small[ROWS*128];
__device__ float g_f[ROWS*Hh], g_gm[ROWS*Hh];
__device__ __nv_bfloat16 g_g1h[ROWS*HDd], g_g1l[ROWS*HDd];
__device__ float g_attn[ROWS*Dm], g_gate[ROWS*Dm];
__device__ __nv_bfloat16 g_lnh[ROWS*Dm], g_lnl[ROWS*Dm];

__device__ __forceinline__ float sigmoidf_(float z) { return 1.f / (1.f + expf(-z)); }

__device__ __forceinline__ void split2(float x, __nv_bfloat16& h, __nv_bfloat16& l) {
    h = __float2bfloat16(x);
    l = __float2bfloat16(x - __bfloat162float(h));
}

// ---------------- fp32 -> bf16 hi/lo split ----------------
__global__ void split_k(const float* __restrict__ s, __nv_bfloat16* __restrict__ h,
                        __nv_bfloat16* __restrict__ l, int n4)
{
    int i = blockIdx.x * 256 + threadIdx.x;
    if (i >= n4) return;
    float4 v = ((const float4*)s)[i];
    __nv_bfloat16 hh[4], ll[4];
    split2(v.x, hh[0], ll[0]); split2(v.y, hh[1], ll[1]);
    split2(v.z, hh[2], ll[2]); split2(v.w, hh[3], ll[3]);
    ((__nv_bfloat162*)h)[i*2]   = __nv_bfloat162(hh[0], hh[1]);
    ((__nv_bfloat162*)h)[i*2+1] = __nv_bfloat162(hh[2], hh[3]);
    ((__nv_bfloat162*)l)[i*2]   = __nv_bfloat162(ll[0], ll[1]);
    ((__nv_bfloat162*)l)[i*2+1] = __nv_bfloat162(ll[2], ll[3]);
}

// ---------------- pack Wf|Wgamma|Wg1 -> [1024][128] bf16 hi/lo ----------------
__global__ void pack_small_k(const float* __restrict__ Wgamma, const float* __restrict__ Wf,
                             const float* __restrict__ Wg1)
{
    int k = blockIdx.x, j = threadIdx.x;
    float v = 0.f;
    if (j < 16)      v = Wf[k*Hh + j];
    else if (j < 32) v = Wgamma[k*Hh + (j-16)];
    else if (j < 96) v = Wg1[k*HDd + (j-32)];
    __nv_bfloat16 h, l;
    split2(v, h, l);
    g_Wsh[k*128 + j] = h;
    g_Wsl[k*128 + j] = l;
}

// ---------------- post-process small GEMM outputs ----------------
__global__ void postsmall_k()
{
    int row = blockIdx.x, j = threadIdx.x;
    float v = g_small[row*128 + j];
    if (j < 16)      g_f[row*Hh + j]        = sigmoidf_(v);   // exp(log_sigmoid) = sigmoid
    else if (j < 32) g_gm[row*Hh + (j-16)]  = -sigmoidf_(v);
    else if (j < 96) {
        __nv_bfloat16 h, l; split2(v, h, l);
        g_g1h[row*HDd + (j-32)] = h;
        g_g1l[row*HDd + (j-32)] = l;
    }
}

// ================= bf16 split-precision MMA GEMM =================
// C[M,N] = act( (Ah+Al)[M,K] @ (Bh+Bl)[K,N] ), via AhBh + AhBl + AlBh.
// BM=128, BN=128, BK=32, 256 threads (8 warps, 2x4), warp tile 64x32.
#define SA 40
#define SB 136
#define ASZ (128*SA)
#define BSZ (32*SB)
#define MMA_SMEM ((4*ASZ + 4*BSZ) * 2)

#define LDSM4(R0,R1,R2,R3,addr) asm volatile( \
  "ldmatrix.sync.aligned.m8n8.x4.shared.b16 {%0,%1,%2,%3}, [%4];" \
  : "=r"(R0),"=r"(R1),"=r"(R2),"=r"(R3) : "r"(addr))
#define LDSM4T(R0,R1,R2,R3,addr) asm volatile( \
  "ldmatrix.sync.aligned.m8n8.x4.trans.shared.b16 {%0,%1,%2,%3}, [%4];" \
  : "=r"(R0),"=r"(R1),"=r"(R2),"=r"(R3) : "r"(addr))
#define MMA16816(C,A,B0,B1) asm volatile( \
  "mma.sync.aligned.m16n8k16.row.col.f32.bf16.bf16.f32 " \
  "{%0,%1,%2,%3}, {%4,%5,%6,%7}, {%8,%9}, {%0,%1,%2,%3};" \
  : "+f"((C)[0]),"+f"((C)[1]),"+f"((C)[2]),"+f"((C)[3]) \
  : "r"((A)[0]),"r"((A)[1]),"r"((A)[2]),"r"((A)[3]),"r"(B0),"r"(B1))

__global__ __launch_bounds__(256,1) void mma_gemm(
    const __nv_bfloat16* __restrict__ Ah, const __nv_bfloat16* __restrict__ Al,
    const __nv_bfloat16* __restrict__ Bh, const __nv_bfloat16* __restrict__ Bl,
    float* __restrict__ C, int M, int N, int K, int act)
{
    extern __shared__ __nv_bfloat16 sm[];
    __nv_bfloat16* sAh = sm;
    __nv_bfloat16* sAl = sAh + 2*ASZ;
    __nv_bfloat16* sBh = sAl + 2*ASZ;
    __nv_bfloat16* sBl = sBh + 2*BSZ;

    const int tid  = threadIdx.x;
    const int lane = tid & 31, warp = tid >> 5;
    const int wm = warp & 1, wn = warp >> 1;
    const int m0 = blockIdx.y * 128, n0 = blockIdx.x * 128;

    float acc[4][4][4];
#pragma unroll
    for (int i = 0; i < 4; i++)
#pragma unroll
        for (int j = 0; j < 4; j++)
#pragma unroll
            for (int t = 0; t < 4; t++) acc[i][j][t] = 0.f;

    const int NIT = K >> 5;

    uint4 pah[2], pal[2], pbh[2], pbl[2];

    // ---- initial tile load (it=0) ----
#pragma unroll
    for (int p = 0; p < 2; p++) {
        int s = tid + p*256;
        {   int r = s >> 2, c = (s & 3) * 8;
            size_t off = (size_t)(m0 + r) * K + c;
            pah[p] = *(const uint4*)(Ah + off);
            pal[p] = *(const uint4*)(Al + off); }
        {   int r = s >> 4, c = (s & 15) * 8;
            size_t off = (size_t)r * N + n0 + c;
            pbh[p] = *(const uint4*)(Bh + off);
            pbl[p] = *(const uint4*)(Bl + off); }
    }
#pragma unroll
    for (int p = 0; p < 2; p++) {
        int s = tid + p*256;
        {   int r = s >> 2, c = (s & 3) * 8;
            *(uint4*)(sAh + r*SA + c) = pah[p];
            *(uint4*)(sAl + r*SA + c) = pal[p]; }
        {   int r = s >> 4, c = (s & 15) * 8;
            *(uint4*)(sBh + r*SB + c) = pbh[p];
            *(uint4*)(sBl + r*SB + c) = pbl[p]; }
    }
    __syncthreads();

    int buf = 0;
    for (int it = 0; it < NIT; ++it) {
        const bool more = (it + 1 < NIT);
        if (more) {
            const int k0 = (it + 1) * 32;
#pragma unroll
            for (int p = 0; p < 2; p++) {
                int s = tid + p*256;
                {   int r = s >> 2, c = (s & 3) * 8;
                    size_t off = (size_t)(m0 + r) * K + k0 + c;
                    pah[p] = *(const uint4*)(Ah + off);
                    pal[p] = *(const uint4*)(Al + off); }
                {   int r = s >> 4, c = (s & 15) * 8;
                    size_t off = (size_t)(k0 + r) * N + n0 + c;
                    pbh[p] = *(const uint4*)(Bh + off);
                    pbl[p] = *(const uint4*)(Bl + off); }
            }
        }

        // ---- compute on buf ----
        const __nv_bfloat16* bAh = sAh + buf*ASZ;
        const __nv_bfloat16* bAl = sAl + buf*ASZ;
        const __nv_bfloat16* bBh = sBh + buf*BSZ;
        const __nv_bfloat16* bBl = sBl + buf*BSZ;
#pragma unroll
        for (int step = 0; step < 2; ++step) {
            unsigned afh[4][4], afl[4][4], bfh[4][2], bfl[4][2];
            const int arow = lane & 15;
            const int kc   = step*16 + (lane >> 4)*8;
#pragma unroll
            for (int mt = 0; mt < 4; mt++) {
                unsigned ah_ = (unsigned)__cvta_generic_to_shared(
                    bAh + (wm*64 + mt*16 + arow)*SA + kc);
                LDSM4(afh[mt][0], afh[mt][1], afh[mt][2], afh[mt][3], ah_);
                unsigned al_ = (unsigned)__cvta_generic_to_shared(
                    bAl + (wm*64 + mt*16 + arow)*SA + kc);
                LDSM4(afl[mt][0], afl[mt][1], afl[mt][2], afl[mt][3], al_);
            }
            const int brow = step*16 + (lane & 15);
#pragma unroll
            for (int np = 0; np < 2; np++) {
                const int bc = wn*32 + np*16 + (lane >> 4)*8;
                unsigned bh_ = (unsigned)__cvta_generic_to_shared(bBh + brow*SB + bc);
                unsigned r0,r1,r2,r3;
                LDSM4T(r0, r1, r2, r3, bh_);
                bfh[np*2][0] = r0; bfh[np*2][1] = r1;
                bfh[np*2+1][0] = r2; bfh[np*2+1][1] = r3;
                unsigned bl_ = (unsigned)__cvta_generic_to_shared(bBl + brow*SB + bc);
                LDSM4T(r0, r1, r2, r3, bl_);
                bfl[np*2][0] = r0; bfl[np*2][1] = r1;
                bfl[np*2+1][0] = r2; bfl[np*2+1][1] = r3;
            }
#pragma unroll
            for (int mt = 0; mt < 4; mt++)
#pragma unroll
                for (int nt = 0; nt < 4; nt++) {
                    MMA16816(acc[mt][nt], afh[mt], bfh[nt][0], bfh[nt][1]);
                    MMA16816(acc[mt][nt], afh[mt], bfl[nt][0], bfl[nt][1]);
                    MMA16816(acc[mt][nt], afl[mt], bfh[nt][0], bfh[nt][1]);
                }
        }

        if (more) {
            const int nb = buf ^ 1;
#pragma unroll
            for (int p = 0; p < 2; p++) {
                int s = tid + p*256;
                {   int r = s >> 2, c = (s & 3) * 8;
                    *(uint4*)(sAh + nb*ASZ + r*SA + c) = pah[p];
                    *(uint4*)(sAl + nb*ASZ + r*SA + c) = pal[p]; }
                {   int r = s >> 4, c = (s & 15) * 8;
                    *(uint4*)(sBh + nb*BSZ + r*SB + c) = pbh[p];
                    *(uint4*)(sBl + nb*BSZ + r*SB + c) = pbl[p]; }
            }
        }
        __syncthreads();
        buf ^= 1;
    }

    // ---- epilogue ----
#pragma unroll
    for (int mt = 0; mt < 4; mt++)
#pragma unroll
        for (int nt = 0; nt < 4; nt++) {
            int r = m0 + wm*64 + mt*16 + (lane >> 2);
            int c = n0 + wn*32 + nt*8  + (lane & 3)*2;
            float v0 = acc[mt][nt][0], v1 = acc[mt][nt][1];
            float v2 = acc[mt][nt][2], v3 = acc[mt][nt][3];
            if (act == 1) {
                v0 *= sigmoidf_(v0); v1 *= sigmoidf_(v1);
                v2 *= sigmoidf_(v2); v3 *= sigmoidf_(v3);
            } else if (act == 2) {
                v0 = sigmoidf_(v0); v1 = sigmoidf_(v1);
                v2 = sigmoidf_(v2); v3 = sigmoidf_(v3);
            }
            *(float2*)&C[(size_t)r*N + c]     = make_float2(v0, v1);
            *(float2*)&C[(size_t)(r+8)*N + c] = make_float2(v2, v3);
        }
}

// ---------------- prep: l2norm(k), a = k*gamma*f ----------------
__global__ __launch_bounds__(256) void prep_k()
{
    const int w    = blockIdx.x * 8 + (threadIdx.x >> 5);
    const int lane = threadIdx.x & 31;
    const int bn = w >> 4, h = w & 15;
    const size_t base = (size_t)bn * Dm + h * HDd;
    float k0 = g_k[base + lane];
    float k1 = g_k[base + lane + 32];
    float ss = k0*k0 + k1*k1;
#pragma unroll
    for (int o = 16; o; o >>= 1) ss += __shfl_xor_sync(0xffffffffu, ss, o);
    const float inv = 1.f / fmaxf(sqrtf(ss), 1e-12f);
    const float sc  = g_gm[bn*Hh + h] * g_f[bn*Hh + h];
    k0 *= inv; k1 *= inv;
    g_k[base + lane]      = k0;
    g_k[base + lane + 32] = k1;
    g_a[base + lane]      = k0 * sc;
    g_a[base + lane + 32] = k1 * sc;
}

// ---------------- sequential DPLR delta-rule scan ----------------
// 64 blocks: (b,h,half). 256 threads = 32 v-cols x 8 row-groups (8 rows each).
__global__ __launch_bounds__(256) void scan_k()
{
    const int z = blockIdx.x;           // 0..63
    const int b = z >> 5;
    const int h = (z >> 1) & 15;
    const int half = z & 1;
    const int tid = threadIdx.x;
    const int col = tid >> 3;           // 0..31
    const int sub = tid & 7;            // 0..7
    const int rb  = sub * 8;
    const int colg = half*32 + col;
    const unsigned FULL = 0xffffffffu;

    const int CH = 8;
    __shared__ float sq[CH][64], sk[CH][64], sa[CH][64], sv[CH][32], sf[CH];

    float S[8];
#pragma unroll
    for (int r = 0; r < 8; r++) S[r] = 0.f;

    const size_t base = (size_t)b * Nseq * Dm + h * HDd;

    for (int t0 = 0; t0 < Nseq; t0 += CH) {
        __syncthreads();
#pragma unroll
        for (int j = tid; j < CH*64; j += 256) {
            const int i = j >> 6, e = j & 63;
            const size_t g = base + (size_t)(t0 + i) * Dm + e;
            sq[i][e] = g_q[g];
            sk[i][e] = g_k[g];
            sa[i][e] = g_a[g];
        }
        {
            const int j = tid;
            if (j < CH*32) {
                const int i = j >> 5, e = j & 31;
                sv[i][e] = g_v[base + (size_t)(t0 + i) * Dm + half*32 + e];
            }
        }
        if (tid >= 256 - CH) {
            const int i = tid - (256 - CH);
            sf[i] = g_f[((size_t)b*Nseq + t0 + i) * Hh + h];
        }
        __syncthreads();

        for (int i = 0; i < CH; i++) {
            const float f = sf[i];
            float u0 = 0.f, u1 = 0.f;
#pragma unroll
            for (int r = 0; r < 8; r++) {
                const float t = f * S[r];
                S[r] = t;
                if (r & 1) u1 = fmaf(sa[i][rb + r], t, u1);
                else       u0 = fmaf(sa[i][rb + r], t, u0);
            }
            float u = u0 + u1;
            u += __shfl_xor_sync(FULL, u, 1);
            u += __shfl_xor_sync(FULL, u, 2);
            u += __shfl_xor_sync(FULL, u, 4);
            u += sv[i][col];
#pragma unroll
            for (int r = 0; r < 8; r++)
                S[r] = fmaf(sk[i][rb + r], u, S[r]);
            float o0 = 0.f, o1 = 0.f;
#pragma unroll
            for (int r = 0; r < 8; r++) {
                if (r & 1) o1 = fmaf(sq[i][rb + r], S[r], o1);
                else       o0 = fmaf(sq[i][rb + r], S[r], o0);
            }
            float o = o0 + o1;
            o += __shfl_xor_sync(FULL, o, 1);
            o += __shfl_xor_sync(FULL, o, 2);
            o += __shfl_xor_sync(FULL, o, 4);
            if (sub == 0)
                g_attn[base + (size_t)(t0 + i) * Dm + colg] = o;
        }
    }
}

// ---------------- gate-mul + LayerNorm, emits bf16 hi/lo ----------------
__global__ __launch_bounds__(256) void gateln_k(const float* __restrict__ nw)
{
    const int row = blockIdx.x;
    const int tid = threadIdx.x;
    const int lane = tid & 31, wid = tid >> 5;
    __shared__ float ws[8], ws2[8];

    float vals[4];
    float s = 0.f, s2 = 0.f;
#pragma unroll
    for (int j = 0; j < 4; j++) {
        const int d = tid + j*256;
        const float v = g_attn[(size_t)row*Dm + d] * g_gate[(size_t)row*Dm + d];
        vals[j] = v; s += v; s2 = fmaf(v, v, s2);
    }
#pragma unroll
    for (int o = 16; o; o >>= 1) {
        s  += __shfl_xor_sync(0xffffffffu, s,  o);
        s2 += __shfl_xor_sync(0xffffffffu, s2, o);
    }
    if (lane == 0) { ws[wid] = s; ws2[wid] = s2; }
    __syncthreads();
    float ts = 0.f, ts2 = 0.f;
#pragma unroll
    for (int w = 0; w < 8; w++) { ts += ws[w]; ts2 += ws2[w]; }
    const float mu  = ts * (1.f/Dm);
    const float var = ts2 * (1.f/Dm) - mu*mu;
    const float inv = rsqrtf(var + 1e-5f);
#pragma unroll
    for (int j = 0; j < 4; j++) {
        const int d = tid + j*256;
        const float v = (vals[j] - mu) * inv * nw[d];
        __nv_bfloat16 h, l; split2(v, h, l);
        g_lnh[(size_t)row*Dm + d] = h;
        g_lnl[(size_t)row*Dm + d] = l;
    }
}

// ============================================================
extern "C" void kernel_launch(void* const* d_in, const int* in_sizes, int n_in,
                              void* d_out, int out_size)
{
    const float* x      = (const float*)d_in[0];
    const float* Wq     = (const float*)d_in[1];
    const float* Wk     = (const float*)d_in[2];
    const float* Wv     = (const float*)d_in[3];
    const float* Wgamma = (const float*)d_in[4];
    const float* Wf     = (const float*)d_in[5];
    const float* Wg1    = (const float*)d_in[6];
    const float* Wg2    = (const float*)d_in[7];
    const float* Wo     = (const float*)d_in[8];
    const float* nw     = (const float*)d_in[9];
    float* out = (float*)d_out;

    cudaFuncSetAttribute(mma_gemm, cudaFuncAttributeMaxDynamicSharedMemorySize, MMA_SMEM);

    __nv_bfloat16 *xh, *xl, *Wqh, *Wql, *Wkh, *Wkl, *Wvh, *Wvl, *Woh, *Wol;
    __nv_bfloat16 *Wg2h, *Wg2l, *Wsh, *Wsl, *g1h, *g1l, *lnh, *lnl;
    float *q, *k, *v, *small, *gate;
    cudaGetSymbolAddress((void**)&xh,  g_xh);   cudaGetSymbolAddress((void**)&xl,  g_xl);
    cudaGetSymbolAddress((void**)&Wqh, g_Wqh);  cudaGetSymbolAddress((void**)&Wql, g_Wql);
    cudaGetSymbolAddress((void**)&Wkh, g_Wkh);  cudaGetSymbolAddress((void**)&Wkl, g_Wkl);
    cudaGetSymbolAddress((void**)&Wvh, g_Wvh);  cudaGetSymbolAddress((void**)&Wvl, g_Wvl);
    cudaGetSymbolAddress((void**)&Woh, g_Woh);  cudaGetSymbolAddress((void**)&Wol, g_Wol);
    cudaGetSymbolAddress((void**)&Wg2h, g_Wg2h); cudaGetSymbolAddress((void**)&Wg2l, g_Wg2l);
    cudaGetSymbolAddress((void**)&Wsh, g_Wsh);  cudaGetSymbolAddress((void**)&Wsl, g_Wsl);
    cudaGetSymbolAddress((void**)&g1h, g_g1h);  cudaGetSymbolAddress((void**)&g1l, g_g1l);
    cudaGetSymbolAddress((void**)&lnh, g_lnh);  cudaGetSymbolAddress((void**)&lnl, g_lnl);
    cudaGetSymbolAddress((void**)&q, g_q);      cudaGetSymbolAddress((void**)&k, g_k);
    cudaGetSymbolAddress((void**)&v, g_v);      cudaGetSymbolAddress((void**)&small, g_small);
    cudaGetSymbolAddress((void**)&gate, g_gate);

    // conversions
    split_k<<<(ROWS*Dm/4 + 255)/256, 256>>>(x,  xh,  xl,  ROWS*Dm/4);
    split_k<<<(Dm*Dm/4   + 255)/256, 256>>>(Wq, Wqh, Wql, Dm*Dm/4);
    split_k<<<(Dm*Dm/4   + 255)/256, 256>>>(Wk, Wkh, Wkl, Dm*Dm/4);
    split_k<<<(Dm*Dm/4   + 255)/256, 256>>>(Wv, Wvh, Wvl, Dm*Dm/4);
    split_k<<<(Dm*Dm/4   + 255)/256, 256>>>(Wo, Woh, Wol, Dm*Dm/4);
    split_k<<<(HDd*Dm/4  + 255)/256, 256>>>(Wg2, Wg2h, Wg2l, HDd*Dm/4);
    pack_small_k<<<Dm, 128>>>(Wgamma, Wf, Wg1);

    // projections
    dim3 gbig(Dm/128, ROWS/128);
    mma_gemm<<<gbig, 256, MMA_SMEM>>>(xh, xl, Wqh, Wql, q, ROWS, Dm, Dm, 1);
    mma_gemm<<<gbig, 256, MMA_SMEM>>>(xh, xl, Wkh, Wkl, k, ROWS, Dm, Dm, 1);
    mma_gemm<<<gbig, 256, MMA_SMEM>>>(xh, xl, Wvh, Wvl, v, ROWS, Dm, Dm, 1);
    dim3 gsm(1, ROWS/128);
    mma_gemm<<<gsm, 256, MMA_SMEM>>>(xh, xl, Wsh, Wsl, small, ROWS, 128, Dm, 0);
    postsmall_k<<<ROWS, 128>>>();

    // scan
    prep_k<<<(ROWS*Hh)/8, 256>>>();
    scan_k<<<2*Hh*2, 256>>>();

    // gate + LN + output projection
    mma_gemm<<<gbig, 256, MMA_SMEM>>>(g1h, g1l, Wg2h, Wg2l, gate, ROWS, Dm, HDd, 2);
    gateln_k<<<ROWS, 256>>>(nw);
    mma_gemm<<<gbig, 256, MMA_SMEM>>>(lnh, lnl, Woh, Wol, out, ROWS, Dm, Dm, 0);
}